// round 7
// baseline (speedup 1.0000x reference)
#include <cuda_runtime.h>
#include <cstddef>

// Problem constants (fixed by setup_inputs)
constexpr int B = 8;
constexpr int C = 144;
constexpr int N = 4096;
constexpr int K = 16;
constexpr int G = 9;
constexpr int D = 16;          // C / G
constexpr int NTILE = 64;      // points per block
constexpr int NBLK_N = N / NTILE;

constexpr int FEAT_ELEMS = B * C * N;      // 4718592
constexpr int CENT_ELEMS = B * G * N;      // 294912
constexpr int IDX_ELEMS  = B * N * K;      // 524288
constexpr int NBLOCKS    = B * G * NBLK_N; // 4608 (= CENT_ELEMS / 64)

// Scratch: point-major transposed copies of queryandkey and value.
__device__ __align__(16) float g_qk_t[(size_t)B * G * N * D];
__device__ __align__(16) float g_v_t [(size_t)B * G * N * D];

// Index-dtype flag: 1 if idx_knn is int64, 0 if int32.
__device__ int g_idx_is64;

// ---------------------------------------------------------------------------
// Transpose (B, C, N) -> (B, G, N, D) for both tensors, zero the centrality
// region, and (block 0 only) detect the idx dtype.
// ---------------------------------------------------------------------------
__global__ void __launch_bounds__(256) transpose_kernel(
    const float* __restrict__ qk, const float* __restrict__ val,
    const unsigned int* __restrict__ idx_raw,
    float* __restrict__ cent)
{
    __shared__ float tile[D][NTILE + 1];
    __shared__ unsigned int s_any;

    const int blk   = blockIdx.x;
    const int ntile = blk % NBLK_N;
    const int bg    = blk / NBLK_N;
    const int g     = bg % G;
    const int b     = bg / G;
    const int n0    = ntile * NTILE;
    const int tid   = threadIdx.x;

    // ---- block 0: idx dtype detection (odd words all zero => int64) ----
    if (blk == 0) {
        if (tid == 0) s_any = 0u;
        __syncthreads();
        unsigned int v = idx_raw[2 * tid + 1] |
                         idx_raw[2 * (tid + 256) + 1] |
                         idx_raw[2 * (tid + 512) + 1] |
                         idx_raw[2 * (tid + 768) + 1];
        if (v) atomicOr(&s_any, 1u);
        __syncthreads();
        if (tid == 0) g_idx_is64 = (s_any == 0u) ? 1 : 0;
    }

    // ---- zero this block's 64-element slice of centrality ----
    if (cent != nullptr && tid < 64)
        cent[(size_t)blk * 64 + tid] = 0.0f;

    const size_t src_off = ((size_t)b * C + (size_t)g * D) * N + n0;
    const size_t dst_off = ((size_t)bg * N + n0) * D;

    {
        const float* src = qk + src_off;
        float* dst = g_qk_t + dst_off;
        #pragma unroll
        for (int r = 0; r < 4; r++) {
            int e = tid + r * 256;
            int j = e >> 6, nn = e & 63;
            tile[j][nn] = src[(size_t)j * N + nn];
        }
        __syncthreads();
        #pragma unroll
        for (int r = 0; r < 4; r++) {
            int e = tid + r * 256;
            int nn = e >> 4, j = e & 15;
            dst[nn * D + j] = tile[j][nn];
        }
        __syncthreads();
    }
    {
        const float* src = val + src_off;
        float* dst = g_v_t + dst_off;
        #pragma unroll
        for (int r = 0; r < 4; r++) {
            int e = tid + r * 256;
            int j = e >> 6, nn = e & 63;
            tile[j][nn] = src[(size_t)j * N + nn];
        }
        __syncthreads();
        #pragma unroll
        for (int r = 0; r < 4; r++) {
            int e = tid + r * 256;
            int nn = e >> 4, j = e & 15;
            dst[nn * D + j] = tile[j][nn];
        }
    }
}

// ---------------------------------------------------------------------------
// Main fused kernel: attention + softmax + feature + centrality scatter.
// 4 lanes per point (float4 over the 16 channels), 64 points per 256-thr block.
// Neighbor indices live in smem (broadcast reads) instead of per-thread regs
// to cut register pressure (R6: 80 regs -> occ 35.7%).
// ---------------------------------------------------------------------------
__global__ void __launch_bounds__(256, 4) attn_kernel(
    const void* __restrict__ idx_raw,
    float* __restrict__ out,           // feature region
    float* __restrict__ cent)          // centrality region (may be null)
{
    const float4* __restrict__ qkt = reinterpret_cast<const float4*>(g_qk_t);
    const float4* __restrict__ vt  = reinterpret_cast<const float4*>(g_v_t);

    __shared__ int   s_idx[NTILE][17];   // [point][k], pad 17 -> conflict-free
    __shared__ float ftile[NTILE][D + 1];

    const int blk   = blockIdx.x;
    const int ntile = blk % NBLK_N;
    const int bg    = blk / NBLK_N;
    const int g     = bg % G;
    const int b     = bg / G;
    const int n0    = ntile * NTILE;

    const int tid  = threadIdx.x;
    const int p    = tid >> 2;          // point within tile (0..63)
    const int L    = tid & 3;           // lane within point (4 channels each)
    const int n    = n0 + p;
    const unsigned FULL = 0xffffffffu;

    const size_t bgN = (size_t)bg * N;

    // --- load this lane's 4 neighbor indices (dtype-dispatched), clamp ---
    const size_t ibase = ((size_t)b * N + n) * K + 4 * L;
    int my_idx[4];
    if (g_idx_is64) {
        const long long* ip = reinterpret_cast<const long long*>(idx_raw) + ibase;
        longlong2 e0 = *reinterpret_cast<const longlong2*>(ip);
        longlong2 e1 = *reinterpret_cast<const longlong2*>(ip + 2);
        my_idx[0] = (int)e0.x; my_idx[1] = (int)e0.y;
        my_idx[2] = (int)e1.x; my_idx[3] = (int)e1.y;
    } else {
        int4 e = *reinterpret_cast<const int4*>(
            reinterpret_cast<const int*>(idx_raw) + ibase);
        my_idx[0] = e.x; my_idx[1] = e.y; my_idx[2] = e.z; my_idx[3] = e.w;
    }
    #pragma unroll
    for (int i = 0; i < 4; i++)
        my_idx[i] = min(max(my_idx[i], 0), N - 1);   // structural OOB guard

    // publish indices to smem (row p written/read only by this point's 4 lanes)
    #pragma unroll
    for (int i = 0; i < 4; i++)
        s_idx[p][4 * L + i] = my_idx[i];
    __syncwarp();

    // --- query vector (this lane's 4 channels) ---
    const float4 q = qkt[(bgN + n) * 4 + L];

    // --- attention logits: dot(q, key[m_k]) reduced over 4 lanes ---
    float att[16];
    #pragma unroll
    for (int k = 0; k < 16; k++) {
        int m = s_idx[p][k];            // broadcast LDS
        float4 kk = qkt[(bgN + (size_t)m) * 4 + L];
        float s = fmaf(q.x, kk.x, fmaf(q.y, kk.y, fmaf(q.z, kk.z, q.w * kk.w)));
        s += __shfl_xor_sync(FULL, s, 1);
        s += __shfl_xor_sync(FULL, s, 2);
        att[k] = s;                     // all 4 lanes hold identical value
    }

    // --- softmax over K=16 (redundant per lane, registers only) ---
    float mx = att[0];
    #pragma unroll
    for (int k = 1; k < 16; k++) mx = fmaxf(mx, att[k]);
    float sum = 0.0f;
    #pragma unroll
    for (int k = 0; k < 16; k++) { att[k] = __expf(att[k] - mx); sum += att[k]; }
    const float inv = 1.0f / sum;
    #pragma unroll
    for (int k = 0; k < 16; k++) att[k] *= inv;

    // --- feature: sum_k att[k] * value[m_k] (this lane's 4 channels) ---
    float4 acc = make_float4(0.f, 0.f, 0.f, 0.f);
    #pragma unroll
    for (int k = 0; k < 16; k++) {
        int m = s_idx[p][k];            // broadcast LDS
        float4 vv = vt[(bgN + (size_t)m) * 4 + L];
        acc.x = fmaf(att[k], vv.x, acc.x);
        acc.y = fmaf(att[k], vv.y, acc.y);
        acc.z = fmaf(att[k], vv.z, acc.z);
        acc.w = fmaf(att[k], vv.w, acc.w);
    }

    // --- centrality scatter: each lane handles its own 4 neighbors ---
    if (cent != nullptr) {
        #pragma unroll
        for (int i = 0; i < 4; i++)
            atomicAdd(&cent[bgN + (size_t)my_idx[i]], att[4 * L + i]);
    }

    // --- stage feature in smem, write coalesced in (B, C, N) layout ---
    ftile[p][4 * L + 0] = acc.x;
    ftile[p][4 * L + 1] = acc.y;
    ftile[p][4 * L + 2] = acc.z;
    ftile[p][4 * L + 3] = acc.w;
    __syncthreads();

    float* fout = out + ((size_t)b * C + (size_t)g * D) * N + n0;
    #pragma unroll
    for (int r = 0; r < 4; r++) {
        int e = tid + r * 256;
        int j = e >> 6, nn = e & 63;
        fout[(size_t)j * N + nn] = ftile[nn][j];
    }
}

// ---------------------------------------------------------------------------
// Launch
// ---------------------------------------------------------------------------
extern "C" void kernel_launch(void* const* d_in, const int* in_sizes, int n_in,
                              void* d_out, int out_size)
{
    // Resolve inputs by element count (robust to ordering)
    const float* qk  = nullptr;
    const float* val = nullptr;
    const void*  idx = nullptr;

    for (int i = 0; i < n_in; i++) {
        if (in_sizes[i] == FEAT_ELEMS) {
            if (qk == nullptr)       qk  = (const float*)d_in[i];
            else if (val == nullptr) val = (const float*)d_in[i];
        } else if (in_sizes[i] == IDX_ELEMS) {
            idx = d_in[i];
        }
    }
    if (qk == nullptr || val == nullptr || idx == nullptr) {
        qk  = (const float*)d_in[4];
        val = (const float*)d_in[5];
        idx = d_in[6];
    }

    float* out  = (float*)d_out;                   // feature (B*C*N) first
    float* cent = nullptr;                         // then centrality (B*G*N)
    if (out_size >= FEAT_ELEMS + CENT_ELEMS)
        cent = out + (size_t)FEAT_ELEMS;

    transpose_kernel<<<NBLOCKS, 256>>>(qk, val, (const unsigned int*)idx, cent);
    attn_kernel<<<NBLOCKS, 256>>>(idx, out, cent);
}

// round 8
// speedup vs baseline: 1.2102x; 1.2102x over previous
#include <cuda_runtime.h>
#include <cstddef>

// Problem constants (fixed by setup_inputs)
constexpr int B = 8;
constexpr int C = 144;
constexpr int N = 4096;
constexpr int K = 16;
constexpr int G = 9;
constexpr int D = 16;          // C / G
constexpr int NTILE = 64;      // points per transpose block
constexpr int NBLK_N = N / NTILE;

constexpr int FEAT_ELEMS = B * C * N;      // 4718592
constexpr int CENT_ELEMS = B * G * N;      // 294912
constexpr int IDX_ELEMS  = B * N * K;      // 524288
constexpr int TBLOCKS    = B * G * NBLK_N; // 4608 (= CENT_ELEMS / 64)

constexpr int PTS     = 32;                // points per attn block (8 lanes each)
constexpr int NBLK_A  = N / PTS;           // 128
constexpr int ABLOCKS = B * G * NBLK_A;    // 9216

// Fused scratch: per point one 128B row = [key(16 floats) | value(16 floats)].
// Row (bg, n) starts at ((bg*N + n) * 32) floats — 128B aligned.
__device__ __align__(128) float g_qkv[(size_t)B * G * N * 32];

// Index-dtype flag: 1 if idx_knn is int64, 0 if int32.
__device__ int g_idx_is64;

// ---------------------------------------------------------------------------
// Transpose (B, C, N) -> fused (B*G, N, 32) rows, zero the centrality region,
// and (block 0 only) detect the idx dtype.
// ---------------------------------------------------------------------------
__global__ void __launch_bounds__(256) transpose_kernel(
    const float* __restrict__ qk, const float* __restrict__ val,
    const unsigned int* __restrict__ idx_raw,
    float* __restrict__ cent)
{
    __shared__ float tile[D][NTILE + 1];
    __shared__ unsigned int s_any;

    const int blk   = blockIdx.x;
    const int ntile = blk % NBLK_N;
    const int bg    = blk / NBLK_N;
    const int g     = bg % G;
    const int b     = bg / G;
    const int n0    = ntile * NTILE;
    const int tid   = threadIdx.x;

    // ---- block 0: idx dtype detection (odd words all zero => int64) ----
    if (blk == 0) {
        if (tid == 0) s_any = 0u;
        __syncthreads();
        unsigned int v = idx_raw[2 * tid + 1] |
                         idx_raw[2 * (tid + 256) + 1] |
                         idx_raw[2 * (tid + 512) + 1] |
                         idx_raw[2 * (tid + 768) + 1];
        if (v) atomicOr(&s_any, 1u);
        __syncthreads();
        if (tid == 0) g_idx_is64 = (s_any == 0u) ? 1 : 0;
    }

    // ---- zero this block's 64-element slice of centrality ----
    if (cent != nullptr && tid < 64)
        cent[(size_t)blk * 64 + tid] = 0.0f;

    const size_t src_off = ((size_t)b * C + (size_t)g * D) * N + n0;
    float* dst = g_qkv + ((size_t)bg * N + n0) * 32;

    {   // queryandkey -> row offset [0:16)
        const float* src = qk + src_off;
        #pragma unroll
        for (int r = 0; r < 4; r++) {
            int e = tid + r * 256;
            int j = e >> 6, nn = e & 63;
            tile[j][nn] = src[(size_t)j * N + nn];
        }
        __syncthreads();
        #pragma unroll
        for (int r = 0; r < 4; r++) {
            int e = tid + r * 256;
            int nn = e >> 4, j = e & 15;
            dst[nn * 32 + j] = tile[j][nn];
        }
        __syncthreads();
    }
    {   // value -> row offset [16:32)
        const float* src = val + src_off;
        #pragma unroll
        for (int r = 0; r < 4; r++) {
            int e = tid + r * 256;
            int j = e >> 6, nn = e & 63;
            tile[j][nn] = src[(size_t)j * N + nn];
        }
        __syncthreads();
        #pragma unroll
        for (int r = 0; r < 4; r++) {
            int e = tid + r * 256;
            int nn = e >> 4, j = e & 15;
            dst[nn * 32 + 16 + j] = tile[j][nn];
        }
    }
}

// ---------------------------------------------------------------------------
// Fused attention. 8 lanes per point: lanes 0-3 carry key channels, lanes 4-7
// carry value channels; one 128B gather per (point, neighbor) fetches both.
// Softmax shifted by the first logit (shift-invariant, no max pre-pass).
// ---------------------------------------------------------------------------
__global__ void __launch_bounds__(256, 4) attn_kernel(
    const void* __restrict__ idx_raw,
    float* __restrict__ out,           // feature region
    float* __restrict__ cent)          // centrality region (may be null)
{
    const float4* __restrict__ qkv = reinterpret_cast<const float4*>(g_qkv);

    __shared__ int   s_idx[PTS][17];
    __shared__ float ftile[PTS][D + 1];

    const int blk = blockIdx.x;
    const int nt  = blk % NBLK_A;
    const int bg  = blk / NBLK_A;
    const int g   = bg % G;
    const int b   = bg / G;
    const int n0  = nt * PTS;

    const int tid = threadIdx.x;
    const int p   = tid >> 3;           // point within block (0..31)
    const int L   = tid & 7;            // lane within point (0..7)
    const int n   = n0 + p;
    const int lane = tid & 31;
    const unsigned FULL = 0xffffffffu;

    const size_t bgN = (size_t)bg * N;

    // --- lane L loads neighbors 2L, 2L+1 (dtype-dispatched), clamp ---
    const size_t ibase = ((size_t)b * N + n) * K + 2 * L;
    int i0, i1;
    if (g_idx_is64) {
        longlong2 e = *reinterpret_cast<const longlong2*>(
            reinterpret_cast<const long long*>(idx_raw) + ibase);
        i0 = (int)e.x; i1 = (int)e.y;
    } else {
        int2 e = *reinterpret_cast<const int2*>(
            reinterpret_cast<const int*>(idx_raw) + ibase);
        i0 = e.x; i1 = e.y;
    }
    i0 = min(max(i0, 0), N - 1);
    i1 = min(max(i1, 0), N - 1);
    s_idx[p][2 * L]     = i0;
    s_idx[p][2 * L + 1] = i1;
    __syncwarp();

    // --- query (key-part of own row; lanes 4-7 duplicate lanes 0-3) ---
    const float4 q = qkv[(bgN + n) * 8 + (L & 3)];

    // --- single pass: gather kv row, logit, exp-accumulate value ---
    float att[16];                      // raw logits (for centrality)
    float s0 = 0.0f;                    // shift = first logit
    float sum = 0.0f;
    float4 acc = make_float4(0.f, 0.f, 0.f, 0.f);

    #pragma unroll
    for (int k = 0; k < 16; k++) {
        int m = s_idx[p][k];            // broadcast LDS
        float4 kv = qkv[(bgN + (size_t)m) * 8 + L];   // one 128B line / point
        // dot(q, key) valid in lanes 0-3; reduce there, broadcast to 4-7
        float s = fmaf(q.x, kv.x, fmaf(q.y, kv.y, fmaf(q.z, kv.z, q.w * kv.w)));
        s += __shfl_xor_sync(FULL, s, 1);
        s += __shfl_xor_sync(FULL, s, 2);
        s = __shfl_sync(FULL, s, lane & ~4);          // take from low quad
        att[k] = s;
        if (k == 0) s0 = s;
        float e = __expf(s - s0);       // e = 1 for k == 0
        sum += e;
        acc.x = fmaf(e, kv.x, acc.x);   // value channels live in lanes 4-7
        acc.y = fmaf(e, kv.y, acc.y);
        acc.z = fmaf(e, kv.z, acc.z);
        acc.w = fmaf(e, kv.w, acc.w);
    }
    const float inv = 1.0f / sum;

    // --- centrality: lane L owns neighbors 2L, 2L+1 ---
    if (cent != nullptr) {
        float a0 = __expf(att[2 * L]     - s0) * inv;
        float a1 = __expf(att[2 * L + 1] - s0) * inv;
        atomicAdd(&cent[bgN + (size_t)i0], a0);
        atomicAdd(&cent[bgN + (size_t)i1], a1);
    }

    // --- feature: lanes 4-7 hold the value accumulation ---
    if (L >= 4) {
        int c0 = (L - 4) * 4;
        ftile[p][c0 + 0] = acc.x * inv;
        ftile[p][c0 + 1] = acc.y * inv;
        ftile[p][c0 + 2] = acc.z * inv;
        ftile[p][c0 + 3] = acc.w * inv;
    }
    __syncthreads();

    // --- coalesced write in (B, C, N) layout: 16 rows x 32 points ---
    float* fout = out + ((size_t)b * C + (size_t)g * D) * N + n0;
    #pragma unroll
    for (int r = 0; r < 2; r++) {
        int e = tid + r * 256;
        int j = e >> 5, nn = e & 31;
        fout[(size_t)j * N + nn] = ftile[nn][j];
    }
}

// ---------------------------------------------------------------------------
// Launch
// ---------------------------------------------------------------------------
extern "C" void kernel_launch(void* const* d_in, const int* in_sizes, int n_in,
                              void* d_out, int out_size)
{
    // Resolve inputs by element count (robust to ordering)
    const float* qk  = nullptr;
    const float* val = nullptr;
    const void*  idx = nullptr;

    for (int i = 0; i < n_in; i++) {
        if (in_sizes[i] == FEAT_ELEMS) {
            if (qk == nullptr)       qk  = (const float*)d_in[i];
            else if (val == nullptr) val = (const float*)d_in[i];
        } else if (in_sizes[i] == IDX_ELEMS) {
            idx = d_in[i];
        }
    }
    if (qk == nullptr || val == nullptr || idx == nullptr) {
        qk  = (const float*)d_in[4];
        val = (const float*)d_in[5];
        idx = d_in[6];
    }

    float* out  = (float*)d_out;                   // feature (B*C*N) first
    float* cent = nullptr;                         // then centrality (B*G*N)
    if (out_size >= FEAT_ELEMS + CENT_ELEMS)
        cent = out + (size_t)FEAT_ELEMS;

    transpose_kernel<<<TBLOCKS, 256>>>(qk, val, (const unsigned int*)idx, cent);
    attn_kernel<<<ABLOCKS, 256>>>(idx, out, cent);
}

// round 10
// speedup vs baseline: 1.2142x; 1.0033x over previous
#include <cuda_runtime.h>
#include <cstddef>

// Problem constants (fixed by setup_inputs)
constexpr int B = 8;
constexpr int C = 144;
constexpr int N = 4096;
constexpr int K = 16;
constexpr int G = 9;
constexpr int D = 16;          // C / G
constexpr int NTILE = 64;      // points per transpose block
constexpr int NBLK_N = N / NTILE;

constexpr int FEAT_ELEMS = B * C * N;      // 4718592
constexpr int CENT_ELEMS = B * G * N;      // 294912
constexpr int IDX_ELEMS  = B * N * K;      // 524288
constexpr int TBLOCKS    = B * G * NBLK_N; // 4608 (= CENT_ELEMS / 64)

constexpr int PTS     = 32;                // points per attn block (8 lanes each)
constexpr int NBLK_A  = N / PTS;           // 128
constexpr int ABLOCKS = B * G * NBLK_A;    // 9216

// Fused scratch: per point one 128B row = [key(16 floats) | value(16 floats)].
__device__ __align__(128) float g_qkv[(size_t)B * G * N * 32];

// Index-dtype flag: 1 if idx_knn is int64, 0 if int32.
__device__ int g_idx_is64;

// ---------------------------------------------------------------------------
// Transpose (B, C, N) -> fused (B*G, N, 32) rows, zero the centrality region,
// and (block 0 only) detect the idx dtype.
// ---------------------------------------------------------------------------
__global__ void __launch_bounds__(256) transpose_kernel(
    const float* __restrict__ qk, const float* __restrict__ val,
    const unsigned int* __restrict__ idx_raw,
    float* __restrict__ cent)
{
    __shared__ float tile[D][NTILE + 1];
    __shared__ unsigned int s_any;

    const int blk   = blockIdx.x;
    const int ntile = blk % NBLK_N;
    const int bg    = blk / NBLK_N;
    const int g     = bg % G;
    const int b     = bg / G;
    const int n0    = ntile * NTILE;
    const int tid   = threadIdx.x;

    // ---- block 0: idx dtype detection (odd words all zero => int64) ----
    if (blk == 0) {
        if (tid == 0) s_any = 0u;
        __syncthreads();
        unsigned int v = idx_raw[2 * tid + 1] |
                         idx_raw[2 * (tid + 256) + 1] |
                         idx_raw[2 * (tid + 512) + 1] |
                         idx_raw[2 * (tid + 768) + 1];
        if (v) atomicOr(&s_any, 1u);
        __syncthreads();
        if (tid == 0) g_idx_is64 = (s_any == 0u) ? 1 : 0;
    }

    // ---- zero this block's 64-element slice of centrality ----
    if (cent != nullptr && tid < 64)
        cent[(size_t)blk * 64 + tid] = 0.0f;

    const size_t src_off = ((size_t)b * C + (size_t)g * D) * N + n0;
    float* dst = g_qkv + ((size_t)bg * N + n0) * 32;

    {   // queryandkey -> row offset [0:16)
        const float* src = qk + src_off;
        #pragma unroll
        for (int r = 0; r < 4; r++) {
            int e = tid + r * 256;
            int j = e >> 6, nn = e & 63;
            tile[j][nn] = src[(size_t)j * N + nn];
        }
        __syncthreads();
        #pragma unroll
        for (int r = 0; r < 4; r++) {
            int e = tid + r * 256;
            int nn = e >> 4, j = e & 15;
            dst[nn * 32 + j] = tile[j][nn];
        }
        __syncthreads();
    }
    {   // value -> row offset [16:32)
        const float* src = val + src_off;
        #pragma unroll
        for (int r = 0; r < 4; r++) {
            int e = tid + r * 256;
            int j = e >> 6, nn = e & 63;
            tile[j][nn] = src[(size_t)j * N + nn];
        }
        __syncthreads();
        #pragma unroll
        for (int r = 0; r < 4; r++) {
            int e = tid + r * 256;
            int nn = e >> 4, j = e & 15;
            dst[nn * 32 + 16 + j] = tile[j][nn];
        }
    }
}

// ---------------------------------------------------------------------------
// Fused attention. 8 lanes per point: lanes 0-3 carry key channels, lanes 4-7
// carry value channels; one 128B gather per (point, neighbor) fetches both.
// Softmax shifted by the first logit (shift-invariant, no max pre-pass).
// Lane L keeps only the exps of ITS two neighbors (k=2L, 2L+1) in registers
// (predicated select per unrolled k) instead of an att[16] array.
// ---------------------------------------------------------------------------
__global__ void __launch_bounds__(256, 5) attn_kernel(
    const void* __restrict__ idx_raw,
    float* __restrict__ out,           // feature region
    float* __restrict__ cent)          // centrality region (may be null)
{
    const float4* __restrict__ qkv = reinterpret_cast<const float4*>(g_qkv);

    __shared__ int   s_idx[PTS][17];
    __shared__ float ftile[PTS][D + 1];

    const int blk = blockIdx.x;
    const int nt  = blk % NBLK_A;
    const int bg  = blk / NBLK_A;
    const int g   = bg % G;
    const int b   = bg / G;
    const int n0  = nt * PTS;

    const int tid = threadIdx.x;
    const int p   = tid >> 3;           // point within block (0..31)
    const int L   = tid & 7;            // lane within point (0..7)
    const int n   = n0 + p;
    const int lane = tid & 31;
    const unsigned FULL = 0xffffffffu;

    const size_t bgN = (size_t)bg * N;

    // --- lane L loads neighbors 2L, 2L+1 (dtype-dispatched), clamp ---
    const size_t ibase = ((size_t)b * N + n) * K + 2 * L;
    int i0, i1;
    if (g_idx_is64) {
        longlong2 e = *reinterpret_cast<const longlong2*>(
            reinterpret_cast<const long long*>(idx_raw) + ibase);
        i0 = (int)e.x; i1 = (int)e.y;
    } else {
        int2 e = *reinterpret_cast<const int2*>(
            reinterpret_cast<const int*>(idx_raw) + ibase);
        i0 = e.x; i1 = e.y;
    }
    i0 = min(max(i0, 0), N - 1);
    i1 = min(max(i1, 0), N - 1);
    s_idx[p][2 * L]     = i0;
    s_idx[p][2 * L + 1] = i1;
    __syncwarp();

    // --- query (key-part of own row; lanes 4-7 duplicate lanes 0-3) ---
    const float4 q = qkv[(bgN + n) * 8 + (L & 3)];

    // --- single pass: gather kv row, logit, exp-accumulate value ---
    float s0 = 0.0f;                    // shift = first logit
    float sum = 0.0f;
    float my_e0 = 0.0f, my_e1 = 0.0f;   // exps of this lane's own 2 neighbors
    float4 acc = make_float4(0.f, 0.f, 0.f, 0.f);

    #pragma unroll
    for (int k = 0; k < 16; k++) {
        int m = s_idx[p][k];            // broadcast LDS
        float4 kv = qkv[(bgN + (size_t)m) * 8 + L];   // one 128B line / point
        // dot(q, key) valid in lanes 0-3; reduce there, broadcast to 4-7
        float s = fmaf(q.x, kv.x, fmaf(q.y, kv.y, fmaf(q.z, kv.z, q.w * kv.w)));
        s += __shfl_xor_sync(FULL, s, 1);
        s += __shfl_xor_sync(FULL, s, 2);
        s = __shfl_sync(FULL, s, lane & ~4);          // take from low quad
        if (k == 0) s0 = s;
        float e = __expf(s - s0);       // e = 1 for k == 0
        if (2 * L == k)     my_e0 = e;  // compile-time k: ISETP + SEL
        if (2 * L + 1 == k) my_e1 = e;
        sum += e;
        acc.x = fmaf(e, kv.x, acc.x);   // value channels live in lanes 4-7
        acc.y = fmaf(e, kv.y, acc.y);
        acc.z = fmaf(e, kv.z, acc.z);
        acc.w = fmaf(e, kv.w, acc.w);
    }
    const float inv = 1.0f / sum;

    // --- centrality: lane L owns neighbors 2L, 2L+1 ---
    if (cent != nullptr) {
        atomicAdd(&cent[bgN + (size_t)i0], my_e0 * inv);
        atomicAdd(&cent[bgN + (size_t)i1], my_e1 * inv);
    }

    // --- feature: lanes 4-7 hold the value accumulation ---
    if (L >= 4) {
        int c0 = (L - 4) * 4;
        ftile[p][c0 + 0] = acc.x * inv;
        ftile[p][c0 + 1] = acc.y * inv;
        ftile[p][c0 + 2] = acc.z * inv;
        ftile[p][c0 + 3] = acc.w * inv;
    }
    __syncthreads();

    // --- coalesced write in (B, C, N) layout: 16 rows x 32 points ---
    float* fout = out + ((size_t)b * C + (size_t)g * D) * N + n0;
    #pragma unroll
    for (int r = 0; r < 2; r++) {
        int e = tid + r * 256;
        int j = e >> 5, nn = e & 31;
        fout[(size_t)j * N + nn] = ftile[nn][j];
    }
}

// ---------------------------------------------------------------------------
// Launch
// ---------------------------------------------------------------------------
extern "C" void kernel_launch(void* const* d_in, const int* in_sizes, int n_in,
                              void* d_out, int out_size)
{
    // Resolve inputs by element count (robust to ordering)
    const float* qk  = nullptr;
    const float* val = nullptr;
    const void*  idx = nullptr;

    for (int i = 0; i < n_in; i++) {
        if (in_sizes[i] == FEAT_ELEMS) {
            if (qk == nullptr)       qk  = (const float*)d_in[i];
            else if (val == nullptr) val = (const float*)d_in[i];
        } else if (in_sizes[i] == IDX_ELEMS) {
            idx = d_in[i];
        }
    }
    if (qk == nullptr || val == nullptr || idx == nullptr) {
        qk  = (const float*)d_in[4];
        val = (const float*)d_in[5];
        idx = d_in[6];
    }

    float* out  = (float*)d_out;                   // feature (B*C*N) first
    float* cent = nullptr;                         // then centrality (B*G*N)
    if (out_size >= FEAT_ELEMS + CENT_ELEMS)
        cent = out + (size_t)FEAT_ELEMS;

    transpose_kernel<<<TBLOCKS, 256>>>(qk, val, (const unsigned int*)idx, cent);
    attn_kernel<<<ABLOCKS, 256>>>(idx, out, cent);
}